// round 15
// baseline (speedup 1.0000x reference)
#include <cuda_runtime.h>
#include <cstdint>

// ---------------- problem / tiling constants ----------------
#define NN 8192
#define SS 3
#define DD 32
#define KSPLIT 8
#define KPER (NN / KSPLIT)            // 1024 K per item
#define BM 128
#define BK 32
#define SPI (KPER / BK)               // 32 stages per item
#define NPART (SS * KSPLIT)           // 24 partials per output element

// smem layout (floats). Row stride 36: fragment bank = (4r+c)%32, conflict-free;
// 144B rows keep 16B cp.async alignment.
#define SROW 36
#define SA_FLOATS (BM * SROW)                  // 4608
#define SB_FLOATS (DD * SROW)                  // 1152
#define BBASE (4 * SA_FLOATS)                  // 4 stages
#define SMEM_FLOATS (BBASE + 4 * SB_FLOATS)    // 23040 floats -> 92160 B

// ---------------- scratch (no cudaMalloc allowed) ----------------
__device__ float g_preT[SS * DD * NN];          // preT[s][o][n], tf32-rn, 3 MB
__device__ float g_part2[(size_t)NN * DD * NPART];  // [m*32+o][p], 25 MB

// tf32 round-to-nearest: +0x1000 into bit 12; MMA HW truncates low 13 bits.
__device__ __forceinline__ uint32_t tf32rn(uint32_t u) { return u + 0x1000u; }

// ---------------- cp.async helpers (L2::256B prefetch hint) ----------------
__device__ __forceinline__ void cp16(uint32_t saddr, const float* g) {
    asm volatile("cp.async.cg.shared.global.L2::256B [%0], [%1], 16;"
                 :: "r"(saddr), "l"(g) : "memory");
}
__device__ __forceinline__ void cp_commit() {
    asm volatile("cp.async.commit_group;" ::: "memory");
}
__device__ __forceinline__ void cp_wait2() {
    asm volatile("cp.async.wait_group 2;" ::: "memory");
}

// ---------------------------------------------------------------------------
// Kernel 1: preT[s][o][n] = rn_tf32( b[s][o] + sum_i x[n][i]*W[s][i][o] )
// Grid (32, 3), 256 thr; thread owns one n-row (x in regs), 32 outputs.
// ---------------------------------------------------------------------------
__global__ __launch_bounds__(256) void pre_kernel(const float* __restrict__ x,
                                                  const float* __restrict__ W,
                                                  const float* __restrict__ b) {
    __shared__ float sx[256 * 33];
    __shared__ float sW[DD * DD];
    __shared__ float sb[DD];

    int s = blockIdx.y, n0 = blockIdx.x * 256;
    int t = threadIdx.x;

    for (int i = t; i < 256 * DD; i += 256) {
        int row = i >> 5, col = i & 31;
        sx[row * 33 + col] = x[(size_t)n0 * DD + i];
    }
    for (int i = t; i < DD * DD; i += 256) sW[i] = W[s * DD * DD + i];
    if (t < DD) sb[t] = b[s * DD + t];
    __syncthreads();

    float xr[DD];
#pragma unroll
    for (int i = 0; i < DD; i++) xr[i] = sx[t * 33 + i];

#pragma unroll
    for (int oc = 0; oc < 4; oc++) {
        float acc[8];
#pragma unroll
        for (int j = 0; j < 8; j++) acc[j] = sb[oc * 8 + j];
#pragma unroll
        for (int i = 0; i < DD; i++) {
#pragma unroll
            for (int j = 0; j < 8; j++)
                acc[j] = fmaf(xr[i], sW[i * DD + oc * 8 + j], acc[j]);
        }
#pragma unroll
        for (int j = 0; j < 8; j++)
            g_preT[(size_t)(s * DD + oc * 8 + j) * NN + n0 + t] =
                __uint_as_float(tf32rn(__float_as_uint(acc[j])));
    }
}

// ---------------------------------------------------------------------------
// Kernel 2: tf32 mma.sync GEMM (R6 shape), cp.async 4-buffer pipeline, lead 3,
// SINGLE barrier per stage, static grid (64, 3, 8).
//   partial2[(m*32+o)*24 + s*KSPLIT+z] = sum_{k in chunk} adj[s][m][k]*pre[s][k][o]
// ---------------------------------------------------------------------------
__global__ void __launch_bounds__(256, 2) gemm_kernel(const float* __restrict__ adj) {
    extern __shared__ float smem[];
    const uint32_t sbase = (uint32_t)__cvta_generic_to_shared(smem);

    const int t = threadIdx.x;
    const int wid = t >> 5, lane = t & 31;
    const int mt = blockIdx.x, s = blockIdx.y, z = blockIdx.z;

    const float* aB = adj + ((size_t)(s * NN + mt * BM)) * NN + (size_t)z * KPER;
    const float* bB = g_preT + (size_t)s * DD * NN + (size_t)z * KPER;

    const int b_row = t >> 3, b_gr = t & 7;

    auto issue = [&](int st) {
        int buf = st & 3;
        uint32_t sa = sbase + (buf * SA_FLOATS) * 4;
        uint32_t sb = sbase + (BBASE + buf * SB_FLOATS) * 4;
#pragma unroll
        for (int i = 0; i < 4; i++) {
            int idx = i * 256 + t;
            int row = idx >> 3, gr = idx & 7;
            cp16(sa + (row * SROW + gr * 4) * 4,
                 aB + (size_t)row * NN + st * BK + gr * 4);
        }
        cp16(sb + (b_row * SROW + b_gr * 4) * 4,
             bB + (size_t)b_row * NN + st * BK + b_gr * 4);
    };

    float acc[4][4];
#pragma unroll
    for (int nt = 0; nt < 4; nt++)
#pragma unroll
        for (int j = 0; j < 4; j++) acc[nt][j] = 0.0f;

    const int r = lane >> 2, c = lane & 3;
    const int m0w = wid * 16;

    auto compute = [&](int st) {
        int buf = st & 3;
        const uint32_t* sA = reinterpret_cast<const uint32_t*>(smem + buf * SA_FLOATS);
        const uint32_t* sB = reinterpret_cast<const uint32_t*>(smem + BBASE + buf * SB_FLOATS);
#pragma unroll
        for (int k8 = 0; k8 < BK / 8; k8++) {
            int k0 = k8 * 8;
            uint32_t a0 = tf32rn(sA[(m0w + r) * SROW + k0 + c]);
            uint32_t a1 = tf32rn(sA[(m0w + r + 8) * SROW + k0 + c]);
            uint32_t a2 = tf32rn(sA[(m0w + r) * SROW + k0 + c + 4]);
            uint32_t a3 = tf32rn(sA[(m0w + r + 8) * SROW + k0 + c + 4]);
#pragma unroll
            for (int nt = 0; nt < 4; nt++) {
                uint32_t b0 = sB[(nt * 8 + r) * SROW + k0 + c];
                uint32_t b1 = sB[(nt * 8 + r) * SROW + k0 + c + 4];
                asm volatile(
                    "mma.sync.aligned.m16n8k8.row.col.f32.tf32.tf32.f32 "
                    "{%0,%1,%2,%3}, {%4,%5,%6,%7}, {%8,%9}, {%0,%1,%2,%3};"
                    : "+f"(acc[nt][0]), "+f"(acc[nt][1]),
                      "+f"(acc[nt][2]), "+f"(acc[nt][3])
                    : "r"(a0), "r"(a1), "r"(a2), "r"(a3), "r"(b0), "r"(b1));
            }
        }
    };

    // ---- pipeline: 3 stages in flight ahead of compute ----
    issue(0); cp_commit();
    issue(1); cp_commit();
    issue(2); cp_commit();

#pragma unroll 1
    for (int st = 0; st < SPI; st++) {
        cp_wait2();                 // this thread's stage-st copies retired
        __syncthreads();            // all threads' copies visible; also proves
                                    // compute(st-1) done in every warp ->
                                    // buffer (st+3)&3 is free to overwrite
        if (st + 3 < SPI) issue(st + 3);
        cp_commit();                // one group per iter, even if empty
        compute(st);
    }

    // ---- epilogue: scatter-write partials (p-contiguous layout) ----
    const int p = s * KSPLIT + z;
#pragma unroll
    for (int nt = 0; nt < 4; nt++) {
#pragma unroll
        for (int h = 0; h < 2; h++) {
            int m = mt * BM + m0w + r + 8 * h;
            int o = nt * 8 + 2 * c;
            g_part2[((size_t)m * DD + o) * NPART + p]     = acc[nt][2 * h];
            g_part2[((size_t)m * DD + o + 1) * NPART + p] = acc[nt][2 * h + 1];
        }
    }
}

// ---------------------------------------------------------------------------
// Kernel 3: out[i] = relu(sum of 24 contiguous partials). Fully coalesced:
// thread i reads 96 B (6x float4) at byte offset 96*i.
// ---------------------------------------------------------------------------
__global__ __launch_bounds__(256) void reduce_kernel(float* __restrict__ out) {
    int i = blockIdx.x * 256 + threadIdx.x;
    const float4* b = reinterpret_cast<const float4*>(g_part2 + (size_t)i * NPART);
    float s = 0.0f;
#pragma unroll
    for (int j = 0; j < NPART / 4; j++) {
        float4 v = b[j];
        s += v.x + v.y + v.z + v.w;
    }
    out[i] = fmaxf(s, 0.0f);
}

// ---------------------------------------------------------------------------
// Launch: pre -> gemm (static 64x3x8 grid) -> reduce
// ---------------------------------------------------------------------------
extern "C" void kernel_launch(void* const* d_in, const int* in_sizes, int n_in,
                              void* d_out, int out_size) {
    const float* x   = (const float*)d_in[0];   // [8192, 32]
    const float* adj = (const float*)d_in[1];   // [3, 8192, 8192]
    const float* W   = (const float*)d_in[2];   // [3, 32, 32]
    const float* b   = (const float*)d_in[3];   // [3, 32]
    float* out = (float*)d_out;                 // [8192, 32]

    cudaFuncSetAttribute(gemm_kernel, cudaFuncAttributeMaxDynamicSharedMemorySize,
                         SMEM_FLOATS * 4);

    pre_kernel<<<dim3(NN / 256, SS), 256>>>(x, W, b);
    gemm_kernel<<<dim3(NN / BM, SS, KSPLIT), 256, SMEM_FLOATS * 4>>>(adj);
    reduce_kernel<<<(NN * DD) / 256, 256>>>(out);
}

// round 17
// speedup vs baseline: 1.1679x; 1.1679x over previous
#include <cuda_runtime.h>
#include <cstdint>

// ---------------- problem / tiling constants ----------------
#define NN 8192
#define SS 3
#define DD 32
#define KSPLIT 8
#define KPER (NN / KSPLIT)            // 1024 K per item
#define BM 128
#define BK 32
#define SPI (KPER / BK)               // 32 stages per item
#define NPART (SS * KSPLIT)           // 24 partials
#define NMT (NN / BM)                 // 64 M-tiles

// smem layout (floats). Row stride 36: fragment bank = (4r+c)%32, conflict-free;
// 144B rows keep 16B cp.async alignment.
#define SROW 36
#define SA_FLOATS (BM * SROW)                  // 4608
#define SB_FLOATS (DD * SROW)                  // 1152
#define BBASE (4 * SA_FLOATS)                  // 4 stages
#define SMEM_FLOATS (BBASE + 4 * SB_FLOATS)    // 23040 floats -> 92160 B

// ---------------- scratch (no cudaMalloc allowed) ----------------
__device__ float g_preT[SS * DD * NN];          // preT[s][o][n], tf32-rn, 3 MB
__device__ float g_part[NPART][NN * DD];        // K-split partials, 25 MB
__device__ int   g_cnt[NMT];                    // per-tile completion counters

// tf32 round-to-nearest: +0x1000 into bit 12; MMA HW truncates low 13 bits.
__device__ __forceinline__ uint32_t tf32rn(uint32_t u) { return u + 0x1000u; }

// ---------------- cp.async helpers ----------------
__device__ __forceinline__ void cp16(uint32_t saddr, const float* g) {
    asm volatile("cp.async.cg.shared.global [%0], [%1], 16;"
                 :: "r"(saddr), "l"(g) : "memory");
}
__device__ __forceinline__ void cp_commit() {
    asm volatile("cp.async.commit_group;" ::: "memory");
}
__device__ __forceinline__ void cp_wait2() {
    asm volatile("cp.async.wait_group 2;" ::: "memory");
}

// ---------------------------------------------------------------------------
// Kernel 1: preT[s][o][n] = rn_tf32( b[s][o] + sum_i x[n][i]*W[s][i][o] )
// Grid (128, 3) = 384 blocks (saturates 148 SMs); 64 n-rows per block;
// thread = (n_local, o_group of 8). Also zeroes the tile counters.
// ---------------------------------------------------------------------------
__global__ __launch_bounds__(256) void pre_kernel(const float* __restrict__ x,
                                                  const float* __restrict__ W,
                                                  const float* __restrict__ b) {
    if (blockIdx.x == 0 && blockIdx.y == 0 && threadIdx.x < NMT)
        g_cnt[threadIdx.x] = 0;

    __shared__ float sx[64 * 33];
    __shared__ float sW[DD * DD];
    __shared__ float sb[DD];

    int s = blockIdx.y, n0 = blockIdx.x * 64;
    int t = threadIdx.x;

    for (int i = t; i < 64 * DD; i += 256) {
        int row = i >> 5, col = i & 31;
        sx[row * 33 + col] = x[(size_t)n0 * DD + i];
    }
    for (int i = t; i < DD * DD; i += 256) sW[i] = W[s * DD * DD + i];
    if (t < DD) sb[t] = b[s * DD + t];
    __syncthreads();

    int nl = t & 63, oq = t >> 6;       // 64 rows x 4 o-groups
    float xr[DD];
#pragma unroll
    for (int i = 0; i < DD; i++) xr[i] = sx[nl * 33 + i];

    float acc[8];
#pragma unroll
    for (int j = 0; j < 8; j++) acc[j] = sb[oq * 8 + j];
#pragma unroll
    for (int i = 0; i < DD; i++) {
#pragma unroll
        for (int j = 0; j < 8; j++)
            acc[j] = fmaf(xr[i], sW[i * DD + oq * 8 + j], acc[j]);
    }
#pragma unroll
    for (int j = 0; j < 8; j++)
        g_preT[(size_t)(s * DD + oq * 8 + j) * NN + n0 + nl] =
            __uint_as_float(tf32rn(__float_as_uint(acc[j])));
}

// ---------------------------------------------------------------------------
// Kernel 2: tf32 mma.sync GEMM (exact R6 mainloop) + fused split-K reduction.
// Static grid (64, 3, 8). Each CTA stores its partial (R6 coalesced layout),
// then the 24th-arriving CTA per M-tile sums all 24 partials (p ascending,
// deterministic) and writes relu'd output.
// ---------------------------------------------------------------------------
__global__ void __launch_bounds__(256, 2) gemm_kernel(const float* __restrict__ adj,
                                                      float* __restrict__ out) {
    extern __shared__ float smem[];
    __shared__ int s_old;
    const uint32_t sbase = (uint32_t)__cvta_generic_to_shared(smem);

    const int t = threadIdx.x;
    const int wid = t >> 5, lane = t & 31;
    const int mt = blockIdx.x, s = blockIdx.y, z = blockIdx.z;

    const float* aB = adj + ((size_t)(s * NN + mt * BM)) * NN + (size_t)z * KPER;
    const float* bB = g_preT + (size_t)s * DD * NN + (size_t)z * KPER;

    const int b_row = t >> 3, b_gr = t & 7;

    auto issue = [&](int st) {
        int buf = st & 3;
        uint32_t sa = sbase + (buf * SA_FLOATS) * 4;
        uint32_t sb = sbase + (BBASE + buf * SB_FLOATS) * 4;
#pragma unroll
        for (int i = 0; i < 4; i++) {
            int idx = i * 256 + t;
            int row = idx >> 3, gr = idx & 7;
            cp16(sa + (row * SROW + gr * 4) * 4,
                 aB + (size_t)row * NN + st * BK + gr * 4);
        }
        cp16(sb + (b_row * SROW + b_gr * 4) * 4,
             bB + (size_t)b_row * NN + st * BK + b_gr * 4);
    };

    float acc[4][4];
#pragma unroll
    for (int nt = 0; nt < 4; nt++)
#pragma unroll
        for (int j = 0; j < 4; j++) acc[nt][j] = 0.0f;

    const int r = lane >> 2, c = lane & 3;
    const int m0w = wid * 16;

    auto compute = [&](int st) {
        int buf = st & 3;
        const uint32_t* sA = reinterpret_cast<const uint32_t*>(smem + buf * SA_FLOATS);
        const uint32_t* sB = reinterpret_cast<const uint32_t*>(smem + BBASE + buf * SB_FLOATS);
#pragma unroll
        for (int k8 = 0; k8 < BK / 8; k8++) {
            int k0 = k8 * 8;
            uint32_t a0 = tf32rn(sA[(m0w + r) * SROW + k0 + c]);
            uint32_t a1 = tf32rn(sA[(m0w + r + 8) * SROW + k0 + c]);
            uint32_t a2 = tf32rn(sA[(m0w + r) * SROW + k0 + c + 4]);
            uint32_t a3 = tf32rn(sA[(m0w + r + 8) * SROW + k0 + c + 4]);
#pragma unroll
            for (int nt = 0; nt < 4; nt++) {
                uint32_t b0 = sB[(nt * 8 + r) * SROW + k0 + c];
                uint32_t b1 = sB[(nt * 8 + r) * SROW + k0 + c + 4];
                asm volatile(
                    "mma.sync.aligned.m16n8k8.row.col.f32.tf32.tf32.f32 "
                    "{%0,%1,%2,%3}, {%4,%5,%6,%7}, {%8,%9}, {%0,%1,%2,%3};"
                    : "+f"(acc[nt][0]), "+f"(acc[nt][1]),
                      "+f"(acc[nt][2]), "+f"(acc[nt][3])
                    : "r"(a0), "r"(a1), "r"(a2), "r"(a3), "r"(b0), "r"(b1));
            }
        }
    };

    // ---- pipeline: 3 stages in flight ahead of compute (R6 exact) ----
    issue(0); cp_commit();
    issue(1); cp_commit();
    issue(2); cp_commit();

#pragma unroll 1
    for (int st = 0; st < SPI; st++) {
        cp_wait2();                 // oldest group (stage st) complete
        __syncthreads();            // visible to all warps
        compute(st);
        __syncthreads();            // buffer free before refill
        if (st + 3 < SPI) issue(st + 3);
        cp_commit();                // keeps group count uniform
    }

    // ---- epilogue: R6 coalesced partial store ----
    const int p = s * KSPLIT + z;
    float* po = g_part[p];
#pragma unroll
    for (int nt = 0; nt < 4; nt++) {
#pragma unroll
        for (int h = 0; h < 2; h++) {
            int m = mt * BM + m0w + r + 8 * h;
            float2 v = make_float2(acc[nt][2 * h], acc[nt][2 * h + 1]);
            *reinterpret_cast<float2*>(&po[(size_t)m * DD + nt * 8 + 2 * c]) = v;
        }
    }

    // ---- fused split-K reduction: 24th arriver per tile sums + relu ----
    __threadfence();                          // partials visible before count
    if (t == 0) s_old = atomicAdd(&g_cnt[mt], 1);
    __syncthreads();
    if (s_old == NPART - 1) {
        __threadfence();                      // acquire: see all 23 others
        float4* outv = reinterpret_cast<float4*>(out);
#pragma unroll
        for (int g = 0; g < 4; g++) {
            int fi = mt * (BM * DD / 4) + g * 256 + t;   // float4 index
            float4 a = make_float4(0.f, 0.f, 0.f, 0.f);
#pragma unroll
            for (int q = 0; q < NPART; q++) {            // p ascending: fixed order
                float4 v = reinterpret_cast<const float4*>(g_part[q])[fi];
                a.x += v.x; a.y += v.y; a.z += v.z; a.w += v.w;
            }
            a.x = fmaxf(a.x, 0.f); a.y = fmaxf(a.y, 0.f);
            a.z = fmaxf(a.z, 0.f); a.w = fmaxf(a.w, 0.f);
            outv[fi] = a;
        }
    }
}

// ---------------------------------------------------------------------------
// Launch: pre (384 blocks) -> gemm (64x3x8, fused reduction)
// ---------------------------------------------------------------------------
extern "C" void kernel_launch(void* const* d_in, const int* in_sizes, int n_in,
                              void* d_out, int out_size) {
    const float* x   = (const float*)d_in[0];   // [8192, 32]
    const float* adj = (const float*)d_in[1];   // [3, 8192, 8192]
    const float* W   = (const float*)d_in[2];   // [3, 32, 32]
    const float* b   = (const float*)d_in[3];   // [3, 32]
    float* out = (float*)d_out;                 // [8192, 32]

    cudaFuncSetAttribute(gemm_kernel, cudaFuncAttributeMaxDynamicSharedMemorySize,
                         SMEM_FLOATS * 4);

    pre_kernel<<<dim3(NN / 64, SS), 256>>>(x, W, b);
    gemm_kernel<<<dim3(NN / BM, SS, KSPLIT), 256, SMEM_FLOATS * 4>>>(adj, out);
}